// round 17
// baseline (speedup 1.0000x reference)
#include <cuda_runtime.h>

// inputs (128, 64, 64, 32) fp32 => B=128, N=64 rows/batch, D=2048.
// loss = mean_b( || sum_n att[b,n,:] ||^2 - sum_n <att_n,att_n> ),
// att = x / max(||x||,1e-12) row-wise.
//
// PIPELINED SINGLE-READ: x is read exactly once AND the next subtile's
// loads are issued before each barrier (continuous DRAM/L2 stream).
// Grid 256 = 2 CTAs per batch (half h owns rows 32h..32h+31), NT=512
// (regs ~110 < 128 cap -> double-buffered va/vb possible).
// Warp (rA 0..7, qq 0..1) covers a half-row; thread holds 8 f4 of the row
// and accumulates acc[8] for its 8 fixed columns.

#define BB   128
#define NN   64
#define DD   2048
#define NF4  (DD / 4)      // 512 f4 columns
#define NT   512           // 16 warps
#define HB   2             // CTAs per batch
#define GRID (BB * HB)     // 256
#define ST   4             // subtiles per CTA
#define SR   8             // rows per subtile

__device__ float4       g_s[BB][HB][NF4];  // per-(batch,half) col sums
__device__ float        g_diagp[GRID];
__device__ double       g_part[BB];
__device__ unsigned int g_pair[BB];        // monotonic (never reset)
__device__ unsigned int g_done;            // monotonic (never reset)

__global__ __launch_bounds__(NT, 1) void fused_loss(const float* __restrict__ x,
                                                    float* __restrict__ out) {
    __shared__ float  wsA[2][SR][2];   // double-buffered row half-sumsq
    __shared__ float4 spad[SR][65];    // rA-combine pad (65: bank rotate)
    __shared__ float  w1[NT / 32], w2[NT / 32];
    __shared__ bool   s_2nd, s_last;
    __shared__ double sdd[NT];

    const int bid  = blockIdx.x;
    const int b    = bid >> 1;
    const int h    = bid & 1;
    const int t    = threadIdx.x;
    const int warp = t >> 5;
    const int lane = t & 31;
    const int rA   = warp >> 1;        // row within subtile (0..7)
    const int qq   = warp & 1;         // half of the row (0..1)
    const float4* base4 = reinterpret_cast<const float4*>(x + (size_t)b * NN * DD);
    // this thread's slice base for subtile s: row = h*32 + s*8 + rA
    const float4* pbase = base4 + (size_t)(h * 32 + rA) * NF4 + qq * 256 + lane;

    float4 acc[8];
    #pragma unroll
    for (int j = 0; j < 8; j++) acc[j] = make_float4(0.f, 0.f, 0.f, 0.f);
    float diag = 0.f;                  // only (qq==0, lane==0) threads

    float4 va[8], vb[8];
    #pragma unroll
    for (int j = 0; j < 8; j++) va[j] = pbase[j * 32];   // subtile 0

    // process(cur, s, nxt_or_null): sumsq -> wsA -> prefetch -> barrier ->
    // inv -> FMA into acc. Macro keeps va/vb as pure register arrays.
    #define PROCESS(CUR, S, NXT, DO_PF)                                        \
    {                                                                          \
        float c0 = 0.f, c1 = 0.f, c2 = 0.f, c3 = 0.f;                          \
        c0 += CUR[0].x*CUR[0].x + CUR[0].y*CUR[0].y + CUR[0].z*CUR[0].z + CUR[0].w*CUR[0].w; \
        c1 += CUR[1].x*CUR[1].x + CUR[1].y*CUR[1].y + CUR[1].z*CUR[1].z + CUR[1].w*CUR[1].w; \
        c2 += CUR[2].x*CUR[2].x + CUR[2].y*CUR[2].y + CUR[2].z*CUR[2].z + CUR[2].w*CUR[2].w; \
        c3 += CUR[3].x*CUR[3].x + CUR[3].y*CUR[3].y + CUR[3].z*CUR[3].z + CUR[3].w*CUR[3].w; \
        c0 += CUR[4].x*CUR[4].x + CUR[4].y*CUR[4].y + CUR[4].z*CUR[4].z + CUR[4].w*CUR[4].w; \
        c1 += CUR[5].x*CUR[5].x + CUR[5].y*CUR[5].y + CUR[5].z*CUR[5].z + CUR[5].w*CUR[5].w; \
        c2 += CUR[6].x*CUR[6].x + CUR[6].y*CUR[6].y + CUR[6].z*CUR[6].z + CUR[6].w*CUR[6].w; \
        c3 += CUR[7].x*CUR[7].x + CUR[7].y*CUR[7].y + CUR[7].z*CUR[7].z + CUR[7].w*CUR[7].w; \
        float ss = (c0 + c1) + (c2 + c3);                                      \
        _Pragma("unroll")                                                      \
        for (int o = 16; o; o >>= 1) ss += __shfl_xor_sync(0xffffffffu, ss, o);\
        if (lane == 0) wsA[(S) & 1][rA][qq] = ss;                              \
        if (DO_PF) {                                                           \
            const float4* pn = pbase + (size_t)(((S) + 1) * SR) * NF4;         \
            _Pragma("unroll")                                                  \
            for (int j = 0; j < 8; j++) NXT[j] = pn[j * 32];                   \
        }                                                                      \
        __syncthreads();                                                       \
        const float rs  = wsA[(S) & 1][rA][0] + wsA[(S) & 1][rA][1];           \
        const float inv = rsqrtf(fmaxf(rs, 1e-24f));                           \
        if (qq == 0 && lane == 0) diag += rs * inv * inv;                      \
        _Pragma("unroll")                                                      \
        for (int j = 0; j < 8; j++) {                                          \
            acc[j].x = fmaf(inv, CUR[j].x, acc[j].x);                          \
            acc[j].y = fmaf(inv, CUR[j].y, acc[j].y);                          \
            acc[j].z = fmaf(inv, CUR[j].z, acc[j].z);                          \
            acc[j].w = fmaf(inv, CUR[j].w, acc[j].w);                          \
        }                                                                      \
    }

    PROCESS(va, 0, vb, 1)
    PROCESS(vb, 1, va, 1)
    PROCESS(va, 2, vb, 1)
    PROCESS(vb, 3, va, 0)
    #undef PROCESS

    // ------------- combine acc over the 8 rA groups -> g_s[b][h] ------------
    // Round j: thread writes spad[rA][qq*32+lane]; threads t<64 sum 8 rA
    // entries -> column qq*256 + j*32 + lane of this half's s-vector.
    #pragma unroll 1
    for (int j = 0; j < 8; j++) {
        __syncthreads();               // previous round's reads complete
        spad[rA][qq * 32 + lane] = acc[j];
        __syncthreads();
        if (t < 64) {
            float4 a = spad[0][t];
            #pragma unroll
            for (int r = 1; r < SR; r++) {
                const float4 qv = spad[r][t];
                a.x += qv.x; a.y += qv.y; a.z += qv.z; a.w += qv.w;
            }
            const int col = (t >> 5) * 256 + j * 32 + (t & 31);
            g_s[b][h][col] = a;
        }
    }

    // reduce diag (8 scattered (qq==0,lane==0) threads)
    float v2 = diag;
    #pragma unroll
    for (int o = 16; o; o >>= 1) v2 += __shfl_xor_sync(0xffffffffu, v2, o);
    if (lane == 0) w2[warp] = v2;
    __threadfence();
    __syncthreads();

    // ------------- pair sync: second CTA of batch computes t1 ---------------
    if (t == 0) {
        float t2 = 0.f;
        #pragma unroll
        for (int i = 0; i < NT / 32; i++) t2 += w2[i];
        g_diagp[bid] = t2;
        __threadfence();
        unsigned int old = atomicAdd(&g_pair[b], 1u);
        s_2nd = ((old & 1u) == 1u);
    }
    __syncthreads();
    if (!s_2nd) return;
    __threadfence();

    float v1;
    {   // 512 threads, one f4 column each
        const float4 A = g_s[b][0][t];
        const float4 C = g_s[b][1][t];
        const float sx = A.x + C.x, sy = A.y + C.y;
        const float sz = A.z + C.z, sw = A.w + C.w;
        v1 = sx * sx + sy * sy + sz * sz + sw * sw;
    }
    #pragma unroll
    for (int o = 16; o; o >>= 1) v1 += __shfl_xor_sync(0xffffffffu, v1, o);
    if (lane == 0) w1[warp] = v1;
    __syncthreads();

    if (t == 0) {
        float t1 = 0.f;
        #pragma unroll
        for (int i = 0; i < NT / 32; i++) t1 += w1[i];
        const double t2 = (double)g_diagp[2 * b] + (double)g_diagp[2 * b + 1];
        g_part[b] = (double)t1 - t2;
        __threadfence();
        unsigned int old = atomicAdd(&g_done, 1u);
        s_last = ((old & (unsigned int)(BB - 1)) == (unsigned int)(BB - 1));
    }
    __syncthreads();
    if (!s_last) return;

    // ------------- finisher: combine 128 per-batch doubles ------------------
    __threadfence();
    sdd[t] = (t < BB) ? g_part[t] : 0.0;
    __syncthreads();
    #pragma unroll
    for (int o = 64; o; o >>= 1) {
        if (t < o && t + o < BB) sdd[t] += sdd[t + o];
        __syncthreads();
    }
    if (t == 0) out[0] = (float)(sdd[0] / (double)BB);
}

extern "C" void kernel_launch(void* const* d_in, const int* in_sizes, int n_in,
                              void* d_out, int out_size) {
    (void)in_sizes; (void)n_in; (void)out_size;
    const float* x = (const float*)d_in[0];
    float* out = (float*)d_out;
    fused_loss<<<GRID, NT>>>(x, out);
}